// round 4
// baseline (speedup 1.0000x reference)
#include <cuda_runtime.h>
#include <cuda_bf16.h>
#include <cstdint>

// f_z[b,i] = z[b,i] + sum_{j<i} h[b, i*(i-1)/2 + j] * z[b,j]
// h packed strictly-lower-triangular row-major. HBM-streaming bound.
//
// Warp handles row pair (i, 511-i): combined length 511 -> identical work per
// warp/CTA (perfect wave balance). h read with aligned LDG.128 (+ <=3-elem
// alignment prologue). z held in shared memory SWIZZLED as
//   zs[(j&3)*128 + (j>>2)]
// so the stride-4 per-lane access pattern of the float4 loop becomes
// stride-1 per plane -> zero bank conflicts (R3 showed 4-way conflicts made
// the kernel l1tex-bound at DRAM=46%).

#define DIM 512
#define HLEN ((DIM * (DIM - 1)) / 2)   // 130816
#define THREADS 256
#define WARPS_PER_CTA 8
#define PAIRS (DIM / 2)
#define CTAS_PER_BATCH (PAIRS / WARPS_PER_CTA) // 32

// swizzled scalar read of z[j]
__device__ __forceinline__ float zsw(const float* __restrict__ zs, int j) {
    return zs[((j & 3) << 7) + (j >> 2)];
}

__device__ __forceinline__ float row_dot(const float* __restrict__ hb,
                                         unsigned hoff,
                                         const float* __restrict__ zs,
                                         int len, int lane)
{
    const float* hrow = hb + hoff;
    float s = 0.0f;
    int mis = (int)(hoff & 3u);
    int p = (4 - mis) & 3;                 // scalar prologue count
    if (p > len) p = len;
    if (lane < p) s = hrow[lane] * zsw(zs, lane);

    int n  = len - p;
    int nv = n >> 2;                       // aligned float4 count
    const float4* h4 = (const float4*)(hrow + p);

    // Per-row plane bases: element k of quad v lives at plane (p+k)&3,
    // lane index v + ((p+k)>>2)  -> stride-1 across lanes, conflict-free.
    int b0 = (((p + 0) & 3) << 7) + ((p + 0) >> 2);
    int b1 = (((p + 1) & 3) << 7) + ((p + 1) >> 2);
    int b2 = (((p + 2) & 3) << 7) + ((p + 2) >> 2);
    int b3 = (((p + 3) & 3) << 7) + ((p + 3) >> 2);

    #pragma unroll 2
    for (int v = lane; v < nv; v += 32) {
        float4 hv = __ldcs(h4 + v);
        s = fmaf(hv.x, zs[b0 + v], s);
        s = fmaf(hv.y, zs[b1 + v], s);
        s = fmaf(hv.z, zs[b2 + v], s);
        s = fmaf(hv.w, zs[b3 + v], s);
    }
    int rbase = p + (nv << 2);
    int rem = n & 3;
    if (lane < rem)
        s = fmaf(__ldcs(hrow + rbase + lane), zsw(zs, rbase + lane), s);

    #pragma unroll
    for (int off = 16; off; off >>= 1)
        s += __shfl_xor_sync(0xffffffffu, s, off);
    return s;
}

__global__ __launch_bounds__(THREADS) void LinearMap_kernel(
    const float* __restrict__ z,
    const float* __restrict__ h,
    float* __restrict__ out,
    int out_size)
{
    __shared__ float zs[DIM];   // swizzled: zs[(j&3)*128 + (j>>2)]

    const int b    = blockIdx.x / CTAS_PER_BATCH;
    const int pg   = blockIdx.x % CTAS_PER_BATCH;
    const int tid  = threadIdx.x;
    const int warp = tid >> 5;
    const int lane = tid & 31;

    const float* zb = z + (size_t)b * DIM;
    #pragma unroll
    for (int j = tid; j < DIM; j += THREADS)
        zs[((j & 3) << 7) + (j >> 2)] = zb[j];
    __syncthreads();

    const float* hb = h + (size_t)b * HLEN;
    const int ia = pg * WARPS_PER_CTA + warp;  // short row, 0..255
    const int ib = DIM - 1 - ia;               // long row, 256..511

    float sa = row_dot(hb, (unsigned)(ia * (ia - 1) / 2), zs, ia, lane);
    float sb = row_dot(hb, (unsigned)(ib * (ib - 1) / 2), zs, ib, lane);

    if (lane == 0) {
        float* ob = out + (size_t)b * DIM;
        ob[ia] = zsw(zs, ia) + sa;
        ob[ib] = zsw(zs, ib) + sb;
    }

    // Fold logdet / tail zeroing into this kernel (d_out is poisoned).
    if (blockIdx.x == 0) {
        const int nfz = (int)(gridDim.x / CTAS_PER_BATCH) * DIM;
        for (int k = nfz + tid; k < out_size; k += THREADS) out[k] = 0.0f;
    }
}

extern "C" void kernel_launch(void* const* d_in, const int* in_sizes, int n_in,
                              void* d_out, int out_size)
{
    const float* z = (const float*)d_in[0];   // [batch, 512]
    const float* h = (const float*)d_in[1];   // [batch, 130816]
    float* out = (float*)d_out;

    const int batch = in_sizes[0] / DIM;      // 256

    dim3 grid(batch * CTAS_PER_BATCH);        // 8192 identical CTAs
    LinearMap_kernel<<<grid, THREADS>>>(z, h, out, out_size);
}

// round 5
// speedup vs baseline: 1.3996x; 1.3996x over previous
#include <cuda_runtime.h>
#include <cuda_bf16.h>
#include <cstdint>

// f_z[b,i] = z[b,i] + sum_{j<i} h[b, i*(i-1)/2 + j] * z[b,j]
// h packed strictly-lower-triangular row-major. HBM-streaming bound.
//
// Warp handles row pair (i, 511-i) = 511 elements = <=4 float4/lane.
// ALL h loads for the pair are issued up front as independent predicated
// LDG.128 (MLP_p1 ~ 6) -> DRAM latency fully overlapped; consumption runs
// from registers with 4 independent accumulators. z lives in shared memory
// in a plane-swizzled layout (zs[(j&3)*128 + j>>2]) so the stride-4 lane
// pattern is conflict-free.

#define DIM 512
#define HLEN ((DIM * (DIM - 1)) / 2)   // 130816
#define THREADS 256
#define WARPS_PER_CTA 8
#define CTAS_PER_BATCH 32              // 256 pairs / 8 warps

__device__ __forceinline__ float4 ldg4p(const float4* p, bool pred) {
    float4 r = make_float4(0.f, 0.f, 0.f, 0.f);
    if (pred) r = __ldcs(p);
    return r;
}
__device__ __forceinline__ float ldg1p(const float* p, bool pred) {
    return pred ? __ldcs(p) : 0.f;
}
// swizzled z read (safe for any j in [0,511])
__device__ __forceinline__ float zsw(const float* zs, int j) {
    return zs[((j & 3) << 7) + (j >> 2)];
}

__global__ __launch_bounds__(THREADS) void LinearMap_kernel(
    const float* __restrict__ z,
    const float* __restrict__ h,
    float* __restrict__ out,
    int out_size)
{
    __shared__ float zs[DIM];   // plane-swizzled

    const int b    = blockIdx.x >> 5;          // / 32
    const int pg   = blockIdx.x & 31;
    const int tid  = threadIdx.x;
    const int warp = tid >> 5;
    const int lane = tid & 31;

    const float* zb = z + (size_t)b * DIM;
    #pragma unroll
    for (int j = tid; j < DIM; j += THREADS)
        zs[((j & 3) << 7) + (j >> 2)] = zb[j];
    __syncthreads();

    const int ia = pg * WARPS_PER_CTA + warp;  // 0..255
    const int ib = DIM - 1 - ia;               // 256..511
    const unsigned offa = (unsigned)(ia * (ia - 1) / 2);
    const unsigned offb = (unsigned)(ib * (ib - 1) / 2);

    int pa = (4 - (int)(offa & 3u)) & 3; if (pa > ia) pa = ia;
    int pb = (4 - (int)(offb & 3u)) & 3; if (pb > ib) pb = ib;
    const int na = ia - pa, nb = ib - pb;
    const int nva = na >> 2, nvb = nb >> 2;    // nva<=63, nvb<=127
    const int rema = na & 3,  remb = nb & 3;
    const int rba = pa + (nva << 2);           // remainder base, row a
    const int rbb = pb + (nvb << 2);           // remainder base, row b

    const float* hra = h + (size_t)b * HLEN + offa;
    const float* hrb = h + (size_t)b * HLEN + offb;
    const float4* ha4 = (const float4*)(hra + pa);
    const float4* hb4 = (const float4*)(hrb + pb);

    // ---- front-batched independent loads (entire pair) ----
    float4 a0 = ldg4p(ha4 + lane,      lane      < nva);
    float4 a1 = ldg4p(ha4 + lane + 32, lane + 32 < nva);
    float4 q0 = ldg4p(hb4 + lane,      lane      < nvb);
    float4 q1 = ldg4p(hb4 + lane + 32, lane + 32 < nvb);
    float4 q2 = ldg4p(hb4 + lane + 64, lane + 64 < nvb);
    float4 q3 = ldg4p(hb4 + lane + 96, lane + 96 < nvb);
    float hpa = ldg1p(hra + lane,        lane < pa);
    float hra_r = ldg1p(hra + rba + lane, lane < rema);
    float hpb = ldg1p(hrb + lane,        lane < pb);
    float hrb_r = ldg1p(hrb + rbb + lane, lane < remb);

    // plane bases: element k of quad v -> zs index ((p+k)&3)*128 + ((p+k)>>2) + v
    const int aB0 = (((pa + 0) & 3) << 7) + ((pa + 0) >> 2);
    const int aB1 = (((pa + 1) & 3) << 7) + ((pa + 1) >> 2);
    const int aB2 = (((pa + 2) & 3) << 7) + ((pa + 2) >> 2);
    const int aB3 = (((pa + 3) & 3) << 7) + ((pa + 3) >> 2);
    const int bB0 = (((pb + 0) & 3) << 7) + ((pb + 0) >> 2);
    const int bB1 = (((pb + 1) & 3) << 7) + ((pb + 1) >> 2);
    const int bB2 = (((pb + 2) & 3) << 7) + ((pb + 2) >> 2);
    const int bB3 = (((pb + 3) & 3) << 7) + ((pb + 3) >> 2);

    float s0 = 0.f, s1 = 0.f, s2 = 0.f, s3 = 0.f;
    // row a quads
    s0 = fmaf(a0.x, zs[aB0 + lane], s0);
    s1 = fmaf(a0.y, zs[aB1 + lane], s1);
    s2 = fmaf(a0.z, zs[aB2 + lane], s2);
    s3 = fmaf(a0.w, zs[aB3 + lane], s3);
    s0 = fmaf(a1.x, zs[aB0 + lane + 32], s0);
    s1 = fmaf(a1.y, zs[aB1 + lane + 32], s1);
    s2 = fmaf(a1.z, zs[aB2 + lane + 32], s2);
    s3 = fmaf(a1.w, zs[aB3 + lane + 32], s3);
    // edges row a (h zero-filled when lane inactive; clamp index for safety)
    {
        int je = rba + lane; if (je > 511) je = 511;
        s0 = fmaf(hpa,   zsw(zs, lane), s0);
        s1 = fmaf(hra_r, zsw(zs, je),   s1);
    }
    float suma = s0 + s1 + s2 + s3;

    s0 = s1 = s2 = s3 = 0.f;
    // row b quads
    s0 = fmaf(q0.x, zs[bB0 + lane], s0);
    s1 = fmaf(q0.y, zs[bB1 + lane], s1);
    s2 = fmaf(q0.z, zs[bB2 + lane], s2);
    s3 = fmaf(q0.w, zs[bB3 + lane], s3);
    s0 = fmaf(q1.x, zs[bB0 + lane + 32], s0);
    s1 = fmaf(q1.y, zs[bB1 + lane + 32], s1);
    s2 = fmaf(q1.z, zs[bB2 + lane + 32], s2);
    s3 = fmaf(q1.w, zs[bB3 + lane + 32], s3);
    s0 = fmaf(q2.x, zs[bB0 + lane + 64], s0);
    s1 = fmaf(q2.y, zs[bB1 + lane + 64], s1);
    s2 = fmaf(q2.z, zs[bB2 + lane + 64], s2);
    s3 = fmaf(q2.w, zs[bB3 + lane + 64], s3);
    s0 = fmaf(q3.x, zs[bB0 + lane + 96], s0);
    s1 = fmaf(q3.y, zs[bB1 + lane + 96], s1);
    s2 = fmaf(q3.z, zs[bB2 + lane + 96], s2);
    s3 = fmaf(q3.w, zs[bB3 + lane + 96], s3);
    // edges row b
    {
        int je = rbb + lane; if (je > 511) je = 511;
        s0 = fmaf(hpb,   zsw(zs, lane), s0);
        s1 = fmaf(hrb_r, zsw(zs, je),   s1);
    }
    float sumb = s0 + s1 + s2 + s3;

    // two warp reductions
    #pragma unroll
    for (int off = 16; off; off >>= 1) {
        suma += __shfl_xor_sync(0xffffffffu, suma, off);
        sumb += __shfl_xor_sync(0xffffffffu, sumb, off);
    }

    if (lane == 0) {
        float* ob = out + (size_t)b * DIM;
        ob[ia] = zsw(zs, ia) + suma;
        ob[ib] = zsw(zs, ib) + sumb;
    }

    // logdet / tail zeroing (d_out is poisoned)
    if (blockIdx.x == 0) {
        const int nfz = (int)(gridDim.x >> 5) * DIM;
        for (int k = nfz + tid; k < out_size; k += THREADS) out[k] = 0.0f;
    }
}

extern "C" void kernel_launch(void* const* d_in, const int* in_sizes, int n_in,
                              void* d_out, int out_size)
{
    const float* z = (const float*)d_in[0];   // [batch, 512]
    const float* h = (const float*)d_in[1];   // [batch, 130816]
    float* out = (float*)d_out;

    const int batch = in_sizes[0] / DIM;      // 256

    dim3 grid(batch * CTAS_PER_BATCH);        // 8192 identical CTAs
    LinearMap_kernel<<<grid, THREADS>>>(z, h, out, out_size);
}